// round 6
// baseline (speedup 1.0000x reference)
#include <cuda_runtime.h>
#include <cuda_bf16.h>
#include <math.h>
#include <stdint.h>

// Problem constants
#define TT 2048
#define HH 2048
#define II 1792
#define EE 16
#define TOPK 4
#define RR (TT*TOPK)

// ---------------- scratch ----------------
__device__ __nv_bfloat16 d_xh[(size_t)TT * HH];
__device__ __nv_bfloat16 d_xl[(size_t)TT * HH];
__device__ __nv_bfloat16 d_ACTh[(size_t)RR * II];
__device__ __nv_bfloat16 d_ACTl[(size_t)RR * II];
__device__ float d_Y[(size_t)RR * HH];
__device__ int   d_counts[EE];
__device__ int   d_offsets[EE];
__device__ int   d_cursors[EE];
__device__ int   d_rows[RR];
__device__ int   d_posof[TT * TOPK];
__device__ float d_topw[TT * TOPK];
__device__ int   d_topi[TT * TOPK];

// ---------------- helpers ----------------
__device__ __forceinline__ uint32_t smem_u32(const void* p) {
    return (uint32_t)__cvta_generic_to_shared(p);
}
__device__ __forceinline__ void ldsm_x4(uint32_t* r, uint32_t addr) {
    asm volatile("ldmatrix.sync.aligned.m8n8.x4.shared.b16 {%0,%1,%2,%3}, [%4];"
                 : "=r"(r[0]), "=r"(r[1]), "=r"(r[2]), "=r"(r[3]) : "r"(addr));
}
__device__ __forceinline__ void ldsm_x2t(uint32_t* r, uint32_t addr) {
    asm volatile("ldmatrix.sync.aligned.m8n8.x2.trans.shared.b16 {%0,%1}, [%2];"
                 : "=r"(r[0]), "=r"(r[1]) : "r"(addr));
}
__device__ __forceinline__ void mma_bf16(float* d, const uint32_t* a, const uint32_t* b) {
    asm volatile("mma.sync.aligned.m16n8k16.row.col.f32.bf16.bf16.f32 "
                 "{%0,%1,%2,%3}, {%4,%5,%6,%7}, {%8,%9}, {%0,%1,%2,%3};"
                 : "+f"(d[0]), "+f"(d[1]), "+f"(d[2]), "+f"(d[3])
                 : "r"(a[0]), "r"(a[1]), "r"(a[2]), "r"(a[3]), "r"(b[0]), "r"(b[1]));
}
__device__ __forceinline__ void cp16(uint32_t dst, const void* src, bool valid) {
    int sz = valid ? 16 : 0;
    asm volatile("cp.async.cg.shared.global [%0], [%1], 16, %2;"
                 :: "r"(dst), "l"(src), "r"(sz));
}
__device__ __forceinline__ void cp_commit() {
    asm volatile("cp.async.commit_group;" ::: "memory");
}
__device__ __forceinline__ void cp_wait1() {
    asm volatile("cp.async.wait_group 1;" ::: "memory");
}
__device__ __forceinline__ void cp_wait0() {
    asm volatile("cp.async.wait_group 0;" ::: "memory");
}
__device__ __forceinline__ void split2(float a, float b, uint32_t& h, uint32_t& l) {
    __nv_bfloat16 ha = __float2bfloat16(a), hb = __float2bfloat16(b);
    __nv_bfloat16 la = __float2bfloat16(a - __bfloat162float(ha));
    __nv_bfloat16 lb = __float2bfloat16(b - __bfloat162float(hb));
    __nv_bfloat162 hp = __halves2bfloat162(ha, hb), lp = __halves2bfloat162(la, lb);
    h = *(uint32_t*)&hp; l = *(uint32_t*)&lp;
}

// ---------------- router / routing ----------------
__global__ void zero_counts_kernel() { if (threadIdx.x < EE) d_counts[threadIdx.x] = 0; }

__global__ void router_kernel(const float* __restrict__ x,
                              const float* __restrict__ rw,
                              const float* __restrict__ bias) {
    int warp = (blockIdx.x * blockDim.x + threadIdx.x) >> 5;
    int lane = threadIdx.x & 31;
    if (warp >= TT) return;
    const float* xr = x + (size_t)warp * HH;
    float acc[EE];
#pragma unroll
    for (int e = 0; e < EE; e++) acc[e] = 0.f;
    for (int h = lane; h < HH; h += 32) {
        float xv = __ldg(xr + h);
#pragma unroll
        for (int e = 0; e < EE; e++) acc[e] += xv * __ldg(rw + (size_t)e * HH + h);
    }
#pragma unroll
    for (int e = 0; e < EE; e++) {
        float v = acc[e];
#pragma unroll
        for (int o = 16; o > 0; o >>= 1) v += __shfl_xor_sync(0xffffffffu, v, o);
        acc[e] = v + bias[e];
    }
    if (lane == 0) {
        int idx[TOPK]; float lg[TOPK];
        unsigned used = 0;
        for (int k = 0; k < TOPK; k++) {
            float best = -INFINITY; int bi = 0;
            for (int e = 0; e < EE; e++) {
                if ((used >> e) & 1u) continue;
                if (acc[e] > best) { best = acc[e]; bi = e; }
            }
            used |= 1u << bi; idx[k] = bi; lg[k] = best;
        }
        float mx = lg[0], w[TOPK], s = 0.f;
        for (int k = 0; k < TOPK; k++) { w[k] = expf(lg[k] - mx); s += w[k]; }
        float inv = 1.f / s;
        for (int k = 0; k < TOPK; k++) {
            d_topi[warp * TOPK + k] = idx[k];
            d_topw[warp * TOPK + k] = w[k] * inv;
            atomicAdd(&d_counts[idx[k]], 1);
        }
    }
}

__global__ void scan_kernel() {
    int off = 0;
    for (int e = 0; e < EE; e++) { d_offsets[e] = off; d_cursors[e] = off; off += d_counts[e]; }
}

__global__ void assign_kernel() {
    int t = blockIdx.x * blockDim.x + threadIdx.x;
    if (t >= TT) return;
    for (int k = 0; k < TOPK; k++) {
        int e = d_topi[t * TOPK + k];
        int pos = atomicAdd(&d_cursors[e], 1);
        d_rows[pos] = t;
        d_posof[t * TOPK + k] = pos;
    }
}

// ---------------- pre-split x into bf16 hi/lo ----------------
__global__ void conv_x_kernel(const float* __restrict__ x) {
    size_t i = ((size_t)blockIdx.x * blockDim.x + threadIdx.x) * 4;
    if (i >= (size_t)TT * HH) return;
    float4 v = *(const float4*)(x + i);
    uint32_t h0, l0, h1, l1;
    split2(v.x, v.y, h0, l0);
    split2(v.z, v.w, h1, l1);
    uint2 hu; hu.x = h0; hu.y = h1;
    uint2 lu; lu.x = l0; lu.y = l1;
    *(uint2*)&d_xh[i] = hu;
    *(uint2*)&d_xl[i] = lu;
}

// ---------------- pipelined GEMM (mma.sync, bf16 3-split) ----------------
#define BK 32

// per-stage smem layout (bytes)
#define S_AH   0
#define S_AL   10240
#define S_BST  20480      // staged fp32 B: 2 mats x 32 rows x 272B
#define S_B0H  37888
#define S_B0L  42496
#define S_B1H  47104
#define S_B1L  51712
#define STAGE_BYTES 57344
#define SM_STAGE0 1024    // [0:512) rowidx
#define SMEM_TOTAL (SM_STAGE0 + 2*STAGE_BYTES)

template<int MODE>
__global__ __launch_bounds__(256)
void moe_gemm(const float* __restrict__ Aext,
              const float* __restrict__ W0,
              const float* __restrict__ W1)
{
    constexpr int Kd  = (MODE == 0) ? HH : II;
    constexpr int ldB = (MODE == 0) ? II : HH;
    constexpr int NK  = Kd / BK;

    extern __shared__ __align__(16) char sm[];

    int e = blockIdx.z;
    int cnt = d_counts[e];
    int mblk = blockIdx.y;
    if (mblk * 128 >= cnt) return;
    int off = d_offsets[e];
    int nb = blockIdx.x * ((MODE == 0) ? 64 : 128);

    const float* B0; const float* B1;
    if (MODE == 0) {
        B0 = W0 + (size_t)e * HH * II + nb;
        B1 = W1 + (size_t)e * HH * II + nb;
    } else {
        B0 = W0 + (size_t)e * II * HH + nb;
        B1 = B0 + 64;
    }
    const __nv_bfloat16* srcH = (MODE == 0) ? d_xh : d_ACTh;
    const __nv_bfloat16* srcL = (MODE == 0) ? d_xl : d_ACTl;

    int tid = threadIdx.x, wid = tid >> 5, lane = tid & 31;

    // cache gathered row indices (-1 = invalid)
    int* rowIdx = (int*)sm;
    if (tid < 128) {
        int lr = mblk * 128 + tid;
        int r = -1;
        if (lr < cnt) r = (MODE == 0) ? d_rows[off + lr] : (off + lr);
        rowIdx[tid] = r;
    }
    __syncthreads();

    uint32_t smb = smem_u32(sm);

    auto load_stage = [&](int s, int kc) {
        uint32_t sb = smb + SM_STAGE0 + s * STAGE_BYTES;
        // A: 128 rows x 32 k bf16 per split; 4 x 16B segs per row
#pragma unroll
        for (int i = 0; i < 2; i++) {
            int slot = tid + 256 * i;
            int row = slot >> 2, seg = slot & 3;
            int r = rowIdx[row];
            bool v = r >= 0;
            size_t go = (size_t)(v ? r : 0) * Kd + kc * BK + seg * 8;
            cp16(sb + S_AH + row * 80 + seg * 16, srcH + go, v);
            cp16(sb + S_AL + row * 80 + seg * 16, srcL + go, v);
        }
        // B fp32: 2 mats x 32 rows x 64 floats; 16 x 16B segs per row
#pragma unroll
        for (int i = 0; i < 4; i++) {
            int slot = tid + 256 * i;
            int mat = slot >> 9, rem = slot & 511;
            int row = rem >> 4, seg = rem & 15;
            const float* src = (mat ? B1 : B0) + (size_t)(kc * BK + row) * ldB + seg * 4;
            cp16(sb + S_BST + mat * 8704 + row * 272 + seg * 16, src, true);
        }
        cp_commit();
    };

    auto convert_stage = [&](int s) {
        char* sbp = sm + SM_STAGE0 + s * STAGE_BYTES;
        int mat = tid >> 7, row = (tid >> 2) & 31, q = tid & 3;
        const char* srcb = sbp + S_BST + mat * 8704 + row * 272 + q * 64;
        uint32_t h[8], l[8];
#pragma unroll
        for (int i = 0; i < 4; i++) {
            float4 v = *(const float4*)(srcb + i * 16);
            split2(v.x, v.y, h[i * 2], l[i * 2]);
            split2(v.z, v.w, h[i * 2 + 1], l[i * 2 + 1]);
        }
        char* dh = sbp + (mat ? S_B1H : S_B0H) + row * 144 + q * 32;
        char* dl = sbp + (mat ? S_B1L : S_B0L) + row * 144 + q * 32;
        *(uint4*)dh        = make_uint4(h[0], h[1], h[2], h[3]);
        *(uint4*)(dh + 16) = make_uint4(h[4], h[5], h[6], h[7]);
        *(uint4*)dl        = make_uint4(l[0], l[1], l[2], l[3]);
        *(uint4*)(dl + 16) = make_uint4(l[4], l[5], l[6], l[7]);
    };

    // ---- warp MMA layout (validated in round 1) ----
    int wm = wid & 3, wn = wid >> 2;
    int sub = lane >> 3, lr = lane & 7;
    int a_row0 = wm * 32 + ((sub & 1) << 3) + lr;
    int a_kc   = (sub >> 1) << 3;
    int b_krow = (((lane >> 3) & 1) << 3) + lr;
    int b_nc0  = wn * 32;

    float acc0[2][4][4], acc1[2][4][4];
#pragma unroll
    for (int i = 0; i < 2; i++)
#pragma unroll
        for (int j = 0; j < 4; j++)
#pragma unroll
            for (int c = 0; c < 4; c++) { acc0[i][j][c] = 0.f; acc1[i][j][c] = 0.f; }

    auto mma_stage = [&](int s) {
        uint32_t sb = smb + SM_STAGE0 + s * STAGE_BYTES;
#pragma unroll
        for (int ck = 0; ck < 2; ck++) {
            uint32_t ah[2][4], al[2][4];
#pragma unroll
            for (int am = 0; am < 2; am++) {
                int row = a_row0 + am * 16;
                int col = ck * 16 + a_kc;
                ldsm_x4(ah[am], sb + S_AH + row * 80 + col * 2);
                ldsm_x4(al[am], sb + S_AL + row * 80 + col * 2);
            }
            {
                uint32_t bh[4][2], bl[4][2];
#pragma unroll
                for (int an = 0; an < 4; an++) {
                    int krow = ck * 16 + b_krow;
                    int ncol = b_nc0 + an * 8;
                    ldsm_x2t(bh[an], sb + S_B0H + krow * 144 + ncol * 2);
                    ldsm_x2t(bl[an], sb + S_B0L + krow * 144 + ncol * 2);
                }
#pragma unroll
                for (int am = 0; am < 2; am++)
#pragma unroll
                    for (int an = 0; an < 4; an++) {
                        mma_bf16(acc0[am][an], ah[am], bh[an]);
                        mma_bf16(acc0[am][an], ah[am], bl[an]);
                        mma_bf16(acc0[am][an], al[am], bh[an]);
                    }
            }
            {
                uint32_t bh[4][2], bl[4][2];
#pragma unroll
                for (int an = 0; an < 4; an++) {
                    int krow = ck * 16 + b_krow;
                    int ncol = b_nc0 + an * 8;
                    ldsm_x2t(bh[an], sb + S_B1H + krow * 144 + ncol * 2);
                    ldsm_x2t(bl[an], sb + S_B1L + krow * 144 + ncol * 2);
                }
#pragma unroll
                for (int am = 0; am < 2; am++)
#pragma unroll
                    for (int an = 0; an < 4; an++) {
                        mma_bf16(acc1[am][an], ah[am], bh[an]);
                        mma_bf16(acc1[am][an], ah[am], bl[an]);
                        mma_bf16(acc1[am][an], al[am], bh[an]);
                    }
            }
        }
    };

    // ---- software pipeline (wait -> BARRIER -> read, everywhere) ----
    load_stage(0, 0);
    load_stage(1, 1);
    cp_wait1();
    __syncthreads();          // stage-0 cp.async data visible to ALL threads
    convert_stage(0);
    __syncthreads();          // stage-0 converted B visible

    for (int kc = 0; kc < NK; kc++) {
        int cur = kc & 1;
        mma_stage(cur);
        __syncthreads();      // all warps done reading stage cur
        if (kc + 1 < NK) {
            if (kc + 2 < NK) { load_stage(cur, kc + 2); cp_wait1(); }
            else cp_wait0();
            __syncthreads();  // stage (kc+1) raw data visible to ALL threads
            convert_stage((kc + 1) & 1);
            __syncthreads();  // stage (kc+1) converted B visible
        }
    }

    // ---- epilogue ----
    int lrow = lane >> 2;
    int lcol = (lane & 3) << 1;
#pragma unroll
    for (int am = 0; am < 2; am++) {
#pragma unroll
        for (int hf = 0; hf < 2; hf++) {
            int row = wm * 32 + am * 16 + hf * 8 + lrow;
            int gm = mblk * 128 + row;
            if (gm >= cnt) continue;
            if (MODE == 0) {
                size_t base = (size_t)(off + gm) * II + nb + wn * 32 + lcol;
#pragma unroll
                for (int an = 0; an < 4; an++) {
                    float g0 = acc0[am][an][hf * 2],     u0 = acc1[am][an][hf * 2];
                    float g1 = acc0[am][an][hf * 2 + 1], u1 = acc1[am][an][hf * 2 + 1];
                    float a0 = g0 / (1.f + expf(-g0)) * u0;
                    float a1 = g1 / (1.f + expf(-g1)) * u1;
                    uint32_t h, l;
                    split2(a0, a1, h, l);
                    *(uint32_t*)&d_ACTh[base + an * 8] = h;
                    *(uint32_t*)&d_ACTl[base + an * 8] = l;
                }
            } else {
                size_t base = (size_t)(off + gm) * HH + nb + wn * 32 + lcol;
#pragma unroll
                for (int an = 0; an < 4; an++) {
                    *(float2*)&d_Y[base + an * 8] =
                        make_float2(acc0[am][an][hf * 2], acc0[am][an][hf * 2 + 1]);
                    *(float2*)&d_Y[base + 64 + an * 8] =
                        make_float2(acc1[am][an][hf * 2], acc1[am][an][hf * 2 + 1]);
                }
            }
        }
    }
}

// ---------------- combine ----------------
__global__ void combine_kernel(float* __restrict__ out) {
    int t = blockIdx.x;
    float w[TOPK]; int p[TOPK];
#pragma unroll
    for (int k = 0; k < TOPK; k++) {
        w[k] = d_topw[t * TOPK + k];
        p[k] = d_posof[t * TOPK + k];
    }
    for (int h = threadIdx.x * 4; h < HH; h += blockDim.x * 4) {
        float4 s = make_float4(0, 0, 0, 0);
#pragma unroll
        for (int k = 0; k < TOPK; k++) {
            float4 y = *(const float4*)&d_Y[(size_t)p[k] * HH + h];
            s.x += w[k] * y.x; s.y += w[k] * y.y;
            s.z += w[k] * y.z; s.w += w[k] * y.w;
        }
        *(float4*)&out[(size_t)t * HH + h] = s;
    }
}

// ---------------- launch ----------------
extern "C" void kernel_launch(void* const* d_in, const int* in_sizes, int n_in,
                              void* d_out, int out_size) {
    const float* x    = (const float*)d_in[0];
    const float* rw   = (const float*)d_in[1];
    const float* bias = (const float*)d_in[2];
    const float* gate = (const float*)d_in[3];
    const float* up   = (const float*)d_in[4];
    const float* down = (const float*)d_in[5];
    float* out = (float*)d_out;

    cudaFuncSetAttribute(moe_gemm<0>, cudaFuncAttributeMaxDynamicSharedMemorySize, SMEM_TOTAL);
    cudaFuncSetAttribute(moe_gemm<1>, cudaFuncAttributeMaxDynamicSharedMemorySize, SMEM_TOTAL);

    zero_counts_kernel<<<1, 32>>>();
    router_kernel<<<TT / 8, 256>>>(x, rw, bias);
    scan_kernel<<<1, 1>>>();
    assign_kernel<<<TT / 256, 256>>>();
    conv_x_kernel<<<(TT * HH / 4 + 255) / 256, 256>>>(x);

    // fused gate+up (+SiLU, bf16-split ACT): x = II/64 n-tiles, y = m-tiles, z = experts
    moe_gemm<0><<<dim3(II / 64, 16, EE), 256, SMEM_TOTAL>>>(x, gate, up);
    // down: x = HH/128 n-tiles
    moe_gemm<1><<<dim3(HH / 128, 16, EE), 256, SMEM_TOTAL>>>(nullptr, down, nullptr);

    combine_kernel<<<TT, 256>>>(out);
}

// round 9
// speedup vs baseline: 1.2430x; 1.2430x over previous
#include <cuda_runtime.h>
#include <cuda_fp16.h>
#include <math.h>
#include <stdint.h>

// Problem constants
#define TT 2048
#define HH 2048
#define II 1792
#define EE 16
#define TOPK 4
#define RR (TT*TOPK)

// ---------------- scratch ----------------
__device__ __half d_xh[(size_t)TT * HH];
__device__ __half d_xl[(size_t)TT * HH];
__device__ __half d_ACTh[(size_t)RR * II];
__device__ __half d_ACTl[(size_t)RR * II];
__device__ float d_Y[(size_t)RR * HH];
__device__ int   d_counts[EE];
__device__ int   d_offsets[EE];
__device__ int   d_cursors[EE];
__device__ int   d_rows[RR];
__device__ int   d_posof[TT * TOPK];
__device__ float d_topw[TT * TOPK];
__device__ int   d_topi[TT * TOPK];

// ---------------- helpers ----------------
__device__ __forceinline__ uint32_t smem_u32(const void* p) {
    return (uint32_t)__cvta_generic_to_shared(p);
}
__device__ __forceinline__ void ldsm_x4(uint32_t* r, uint32_t addr) {
    asm volatile("ldmatrix.sync.aligned.m8n8.x4.shared.b16 {%0,%1,%2,%3}, [%4];"
                 : "=r"(r[0]), "=r"(r[1]), "=r"(r[2]), "=r"(r[3]) : "r"(addr));
}
__device__ __forceinline__ void ldsm_x2t(uint32_t* r, uint32_t addr) {
    asm volatile("ldmatrix.sync.aligned.m8n8.x2.trans.shared.b16 {%0,%1}, [%2];"
                 : "=r"(r[0]), "=r"(r[1]) : "r"(addr));
}
__device__ __forceinline__ void mma_f16(float* d, const uint32_t* a, const uint32_t* b) {
    asm volatile("mma.sync.aligned.m16n8k16.row.col.f32.f16.f16.f32 "
                 "{%0,%1,%2,%3}, {%4,%5,%6,%7}, {%8,%9}, {%0,%1,%2,%3};"
                 : "+f"(d[0]), "+f"(d[1]), "+f"(d[2]), "+f"(d[3])
                 : "r"(a[0]), "r"(a[1]), "r"(a[2]), "r"(a[3]), "r"(b[0]), "r"(b[1]));
}
__device__ __forceinline__ void cp16(uint32_t dst, const void* src, bool valid) {
    int sz = valid ? 16 : 0;
    asm volatile("cp.async.cg.shared.global [%0], [%1], 16, %2;"
                 :: "r"(dst), "l"(src), "r"(sz));
}
__device__ __forceinline__ void cp_commit() {
    asm volatile("cp.async.commit_group;" ::: "memory");
}
__device__ __forceinline__ void cp_wait1() {
    asm volatile("cp.async.wait_group 1;" ::: "memory");
}
__device__ __forceinline__ void cp_wait0() {
    asm volatile("cp.async.wait_group 0;" ::: "memory");
}
// split float pair into fp16 hi + fp16 lo (exact residual)
__device__ __forceinline__ void split2h(float a, float b, uint32_t& h, uint32_t& l) {
    __half ha = __float2half(a), hb = __float2half(b);
    __half la = __float2half(a - __half2float(ha));
    __half lb = __float2half(b - __half2float(hb));
    __half2 hp = __halves2half2(ha, hb), lp = __halves2half2(la, lb);
    h = *(uint32_t*)&hp; l = *(uint32_t*)&lp;
}
// fp16 pair (no split)
__device__ __forceinline__ uint32_t pack2h(float a, float b) {
    __half2 p = __halves2half2(__float2half(a), __float2half(b));
    return *(uint32_t*)&p;
}

// ---------------- router / routing ----------------
__global__ void zero_counts_kernel() { if (threadIdx.x < EE) d_counts[threadIdx.x] = 0; }

__global__ void router_kernel(const float* __restrict__ x,
                              const float* __restrict__ rw,
                              const float* __restrict__ bias) {
    int warp = (blockIdx.x * blockDim.x + threadIdx.x) >> 5;
    int lane = threadIdx.x & 31;
    if (warp >= TT) return;
    const float* xr = x + (size_t)warp * HH;
    float acc[EE];
#pragma unroll
    for (int e = 0; e < EE; e++) acc[e] = 0.f;
    for (int h = lane; h < HH; h += 32) {
        float xv = __ldg(xr + h);
#pragma unroll
        for (int e = 0; e < EE; e++) acc[e] += xv * __ldg(rw + (size_t)e * HH + h);
    }
#pragma unroll
    for (int e = 0; e < EE; e++) {
        float v = acc[e];
#pragma unroll
        for (int o = 16; o > 0; o >>= 1) v += __shfl_xor_sync(0xffffffffu, v, o);
        acc[e] = v + bias[e];
    }
    if (lane == 0) {
        int idx[TOPK]; float lg[TOPK];
        unsigned used = 0;
        for (int k = 0; k < TOPK; k++) {
            float best = -INFINITY; int bi = 0;
            for (int e = 0; e < EE; e++) {
                if ((used >> e) & 1u) continue;
                if (acc[e] > best) { best = acc[e]; bi = e; }
            }
            used |= 1u << bi; idx[k] = bi; lg[k] = best;
        }
        float mx = lg[0], w[TOPK], s = 0.f;
        for (int k = 0; k < TOPK; k++) { w[k] = expf(lg[k] - mx); s += w[k]; }
        float inv = 1.f / s;
        for (int k = 0; k < TOPK; k++) {
            d_topi[warp * TOPK + k] = idx[k];
            d_topw[warp * TOPK + k] = w[k] * inv;
            atomicAdd(&d_counts[idx[k]], 1);
        }
    }
}

__global__ void scan_kernel() {
    int off = 0;
    for (int e = 0; e < EE; e++) { d_offsets[e] = off; d_cursors[e] = off; off += d_counts[e]; }
}

__global__ void assign_kernel() {
    int t = blockIdx.x * blockDim.x + threadIdx.x;
    if (t >= TT) return;
    for (int k = 0; k < TOPK; k++) {
        int e = d_topi[t * TOPK + k];
        int pos = atomicAdd(&d_cursors[e], 1);
        d_rows[pos] = t;
        d_posof[t * TOPK + k] = pos;
    }
}

// ---------------- pre-split x into fp16 hi/lo ----------------
__global__ void conv_x_kernel(const float* __restrict__ x) {
    size_t i = ((size_t)blockIdx.x * blockDim.x + threadIdx.x) * 4;
    if (i >= (size_t)TT * HH) return;
    float4 v = *(const float4*)(x + i);
    uint32_t h0, l0, h1, l1;
    split2h(v.x, v.y, h0, l0);
    split2h(v.z, v.w, h1, l1);
    uint2 hu; hu.x = h0; hu.y = h1;
    uint2 lu; lu.x = l0; lu.y = l1;
    *(uint2*)&d_xh[i] = hu;
    *(uint2*)&d_xl[i] = lu;
}

// ---------------- pipelined GEMM (mma.sync fp16, A 2-split, B single) ----------------
#define BK 32

// per-stage smem layout (bytes)
#define S_AH   0          // 128 x 80B
#define S_AL   10240      // 128 x 80B
#define S_BST  20480      // staged fp32 B: 2 mats x 32 rows x 272B
#define S_B0H  37888      // fp16 B mat0: 32 x 144B
#define S_B1H  42496      // fp16 B mat1: 32 x 144B
#define STAGE_BYTES 47104
#define SM_STAGE0 1024    // [0:512) rowidx
#define SMEM_TOTAL (SM_STAGE0 + 2*STAGE_BYTES)

template<int MODE>
__global__ __launch_bounds__(256)
void moe_gemm(const float* __restrict__ Aext,
              const float* __restrict__ W0,
              const float* __restrict__ W1)
{
    constexpr int Kd  = (MODE == 0) ? HH : II;
    constexpr int ldB = (MODE == 0) ? II : HH;
    constexpr int NK  = Kd / BK;

    extern __shared__ __align__(16) char sm[];

    int e = blockIdx.z;
    int cnt = d_counts[e];
    int mblk = blockIdx.y;
    if (mblk * 128 >= cnt) return;
    int off = d_offsets[e];
    int nb = blockIdx.x * ((MODE == 0) ? 64 : 128);

    const float* B0; const float* B1;
    if (MODE == 0) {
        B0 = W0 + (size_t)e * HH * II + nb;
        B1 = W1 + (size_t)e * HH * II + nb;
    } else {
        B0 = W0 + (size_t)e * II * HH + nb;
        B1 = B0 + 64;
    }
    const __half* srcH = (MODE == 0) ? d_xh : d_ACTh;
    const __half* srcL = (MODE == 0) ? d_xl : d_ACTl;

    int tid = threadIdx.x, wid = tid >> 5, lane = tid & 31;

    // cache gathered row indices (-1 = invalid)
    int* rowIdx = (int*)sm;
    if (tid < 128) {
        int lr = mblk * 128 + tid;
        int r = -1;
        if (lr < cnt) r = (MODE == 0) ? d_rows[off + lr] : (off + lr);
        rowIdx[tid] = r;
    }
    __syncthreads();

    uint32_t smb = smem_u32(sm);

    auto load_stage = [&](int s, int kc) {
        uint32_t sb = smb + SM_STAGE0 + s * STAGE_BYTES;
        // A: 128 rows x 32 k fp16 per split; 4 x 16B segs per row
#pragma unroll
        for (int i = 0; i < 2; i++) {
            int slot = tid + 256 * i;
            int row = slot >> 2, seg = slot & 3;
            int r = rowIdx[row];
            bool v = r >= 0;
            size_t go = (size_t)(v ? r : 0) * Kd + kc * BK + seg * 8;
            cp16(sb + S_AH + row * 80 + seg * 16, srcH + go, v);
            cp16(sb + S_AL + row * 80 + seg * 16, srcL + go, v);
        }
        // B fp32: 2 mats x 32 rows x 64 floats; 16 x 16B segs per row
#pragma unroll
        for (int i = 0; i < 4; i++) {
            int slot = tid + 256 * i;
            int mat = slot >> 9, rem = slot & 511;
            int row = rem >> 4, seg = rem & 15;
            const float* src = (mat ? B1 : B0) + (size_t)(kc * BK + row) * ldB + seg * 4;
            cp16(sb + S_BST + mat * 8704 + row * 272 + seg * 16, src, true);
        }
        cp_commit();
    };

    auto convert_stage = [&](int s) {
        char* sbp = sm + SM_STAGE0 + s * STAGE_BYTES;
        // 2 mats x 32 rows x 64 floats = 4096 elems, 16 per thread
        int mat = tid >> 7, row = (tid >> 2) & 31, q = tid & 3;
        const char* srcb = sbp + S_BST + mat * 8704 + row * 272 + q * 64;
        uint32_t h[4];
#pragma unroll
        for (int i = 0; i < 4; i++) {
            float4 v = *(const float4*)(srcb + i * 16);
            h[i] = 0;
            uint32_t p0 = pack2h(v.x, v.y);
            uint32_t p1 = pack2h(v.z, v.w);
            // pack 4 fp16 into 2 u32 slots sequentially
            if (i == 0) { h[0] = p0; h[1] = p1; }
            else if (i == 1) { h[2] = p0; h[3] = p1; }
            else if (i == 2) { h[0] = p0; h[1] = p1; }  // placeholder, fixed below
        }
        // redo cleanly: 16 floats -> 8 u32
        uint32_t o[8];
#pragma unroll
        for (int i = 0; i < 4; i++) {
            float4 v = *(const float4*)(srcb + i * 16);
            o[i * 2]     = pack2h(v.x, v.y);
            o[i * 2 + 1] = pack2h(v.z, v.w);
        }
        char* dh = sbp + (mat ? S_B1H : S_B0H) + row * 144 + q * 32;
        *(uint4*)dh        = make_uint4(o[0], o[1], o[2], o[3]);
        *(uint4*)(dh + 16) = make_uint4(o[4], o[5], o[6], o[7]);
    };

    // ---- warp MMA layout (validated rounds 1/6) ----
    int wm = wid & 3, wn = wid >> 2;
    int sub = lane >> 3, lr = lane & 7;
    int a_row0 = wm * 32 + ((sub & 1) << 3) + lr;
    int a_kc   = (sub >> 1) << 3;
    int b_krow = (((lane >> 3) & 1) << 3) + lr;
    int b_nc0  = wn * 32;

    float acc0[2][4][4], acc1[2][4][4];
#pragma unroll
    for (int i = 0; i < 2; i++)
#pragma unroll
        for (int j = 0; j < 4; j++)
#pragma unroll
            for (int c = 0; c < 4; c++) { acc0[i][j][c] = 0.f; acc1[i][j][c] = 0.f; }

    auto mma_stage = [&](int s) {
        uint32_t sb = smb + SM_STAGE0 + s * STAGE_BYTES;
#pragma unroll
        for (int ck = 0; ck < 2; ck++) {
            uint32_t ah[2][4], al[2][4];
#pragma unroll
            for (int am = 0; am < 2; am++) {
                int row = a_row0 + am * 16;
                int col = ck * 16 + a_kc;
                ldsm_x4(ah[am], sb + S_AH + row * 80 + col * 2);
                ldsm_x4(al[am], sb + S_AL + row * 80 + col * 2);
            }
            {
                uint32_t bh[4][2];
#pragma unroll
                for (int an = 0; an < 4; an++) {
                    int krow = ck * 16 + b_krow;
                    int ncol = b_nc0 + an * 8;
                    ldsm_x2t(bh[an], sb + S_B0H + krow * 144 + ncol * 2);
                }
#pragma unroll
                for (int am = 0; am < 2; am++)
#pragma unroll
                    for (int an = 0; an < 4; an++) {
                        mma_f16(acc0[am][an], ah[am], bh[an]);
                        mma_f16(acc0[am][an], al[am], bh[an]);
                    }
            }
            {
                uint32_t bh[4][2];
#pragma unroll
                for (int an = 0; an < 4; an++) {
                    int krow = ck * 16 + b_krow;
                    int ncol = b_nc0 + an * 8;
                    ldsm_x2t(bh[an], sb + S_B1H + krow * 144 + ncol * 2);
                }
#pragma unroll
                for (int am = 0; am < 2; am++)
#pragma unroll
                    for (int an = 0; an < 4; an++) {
                        mma_f16(acc1[am][an], ah[am], bh[an]);
                        mma_f16(acc1[am][an], al[am], bh[an]);
                    }
            }
        }
    };

    // ---- software pipeline (wait -> BARRIER -> read) ----
    load_stage(0, 0);
    load_stage(1, 1);
    cp_wait1();
    __syncthreads();
    convert_stage(0);
    __syncthreads();

    for (int kc = 0; kc < NK; kc++) {
        int cur = kc & 1;
        mma_stage(cur);
        __syncthreads();
        if (kc + 1 < NK) {
            if (kc + 2 < NK) { load_stage(cur, kc + 2); cp_wait1(); }
            else cp_wait0();
            __syncthreads();
            convert_stage((kc + 1) & 1);
            __syncthreads();
        }
    }

    // ---- epilogue ----
    int lrow = lane >> 2;
    int lcol = (lane & 3) << 1;
#pragma unroll
    for (int am = 0; am < 2; am++) {
#pragma unroll
        for (int hf = 0; hf < 2; hf++) {
            int row = wm * 32 + am * 16 + hf * 8 + lrow;
            int gm = mblk * 128 + row;
            if (gm >= cnt) continue;
            if (MODE == 0) {
                size_t base = (size_t)(off + gm) * II + nb + wn * 32 + lcol;
#pragma unroll
                for (int an = 0; an < 4; an++) {
                    float g0 = acc0[am][an][hf * 2],     u0 = acc1[am][an][hf * 2];
                    float g1 = acc0[am][an][hf * 2 + 1], u1 = acc1[am][an][hf * 2 + 1];
                    float a0 = g0 / (1.f + expf(-g0)) * u0;
                    float a1 = g1 / (1.f + expf(-g1)) * u1;
                    uint32_t h, l;
                    split2h(a0, a1, h, l);
                    *(uint32_t*)&d_ACTh[base + an * 8] = h;
                    *(uint32_t*)&d_ACTl[base + an * 8] = l;
                }
            } else {
                size_t base = (size_t)(off + gm) * HH + nb + wn * 32 + lcol;
#pragma unroll
                for (int an = 0; an < 4; an++) {
                    *(float2*)&d_Y[base + an * 8] =
                        make_float2(acc0[am][an][hf * 2], acc0[am][an][hf * 2 + 1]);
                    *(float2*)&d_Y[base + 64 + an * 8] =
                        make_float2(acc1[am][an][hf * 2], acc1[am][an][hf * 2 + 1]);
                }
            }
        }
    }
}

// ---------------- combine ----------------
__global__ void combine_kernel(float* __restrict__ out) {
    int t = blockIdx.x;
    float w[TOPK]; int p[TOPK];
#pragma unroll
    for (int k = 0; k < TOPK; k++) {
        w[k] = d_topw[t * TOPK + k];
        p[k] = d_posof[t * TOPK + k];
    }
    for (int h = threadIdx.x * 4; h < HH; h += blockDim.x * 4) {
        float4 s = make_float4(0, 0, 0, 0);
#pragma unroll
        for (int k = 0; k < TOPK; k++) {
            float4 y = *(const float4*)&d_Y[(size_t)p[k] * HH + h];
            s.x += w[k] * y.x; s.y += w[k] * y.y;
            s.z += w[k] * y.z; s.w += w[k] * y.w;
        }
        *(float4*)&out[(size_t)t * HH + h] = s;
    }
}

// ---------------- launch ----------------
extern "C" void kernel_launch(void* const* d_in, const int* in_sizes, int n_in,
                              void* d_out, int out_size) {
    const float* x    = (const float*)d_in[0];
    const float* rw   = (const float*)d_in[1];
    const float* bias = (const float*)d_in[2];
    const float* gate = (const float*)d_in[3];
    const float* up   = (const float*)d_in[4];
    const float* down = (const float*)d_in[5];
    float* out = (float*)d_out;

    cudaFuncSetAttribute(moe_gemm<0>, cudaFuncAttributeMaxDynamicSharedMemorySize, SMEM_TOTAL);
    cudaFuncSetAttribute(moe_gemm<1>, cudaFuncAttributeMaxDynamicSharedMemorySize, SMEM_TOTAL);

    zero_counts_kernel<<<1, 32>>>();
    router_kernel<<<TT / 8, 256>>>(x, rw, bias);
    scan_kernel<<<1, 1>>>();
    assign_kernel<<<TT / 256, 256>>>();
    conv_x_kernel<<<(TT * HH / 4 + 255) / 256, 256>>>(x);

    // fused gate+up (+SiLU, fp16-split ACT): x = II/64 n-tiles, y = m-tiles, z = experts
    moe_gemm<0><<<dim3(II / 64, 16, EE), 256, SMEM_TOTAL>>>(x, gate, up);
    // down: x = HH/128 n-tiles
    moe_gemm<1><<<dim3(HH / 128, 16, EE), 256, SMEM_TOTAL>>>(nullptr, down, nullptr);

    combine_kernel<<<TT, 256>>>(out);
}

// round 10
// speedup vs baseline: 1.8322x; 1.4740x over previous
#include <cuda_runtime.h>
#include <cuda_fp16.h>
#include <math.h>
#include <stdint.h>

// Problem constants
#define TT 2048
#define HH 2048
#define II 1792
#define EE 16
#define TOPK 4
#define RR (TT*TOPK)

// ---------------- scratch ----------------
__device__ __half d_xh[(size_t)TT * HH];
__device__ __half d_ACTh[(size_t)RR * II];
__device__ float d_Y[(size_t)RR * HH];
__device__ int   d_counts[EE];
__device__ int   d_offsets[EE];
__device__ int   d_cursors[EE];
__device__ int   d_rows[RR];
__device__ int   d_posof[TT * TOPK];
__device__ float d_topw[TT * TOPK];
__device__ int   d_topi[TT * TOPK];

// ---------------- helpers ----------------
__device__ __forceinline__ uint32_t smem_u32(const void* p) {
    return (uint32_t)__cvta_generic_to_shared(p);
}
__device__ __forceinline__ void ldsm_x4(uint32_t* r, uint32_t addr) {
    asm volatile("ldmatrix.sync.aligned.m8n8.x4.shared.b16 {%0,%1,%2,%3}, [%4];"
                 : "=r"(r[0]), "=r"(r[1]), "=r"(r[2]), "=r"(r[3]) : "r"(addr));
}
__device__ __forceinline__ void ldsm_x2t(uint32_t* r, uint32_t addr) {
    asm volatile("ldmatrix.sync.aligned.m8n8.x2.trans.shared.b16 {%0,%1}, [%2];"
                 : "=r"(r[0]), "=r"(r[1]) : "r"(addr));
}
__device__ __forceinline__ void mma_f16(float* d, const uint32_t* a, const uint32_t* b) {
    asm volatile("mma.sync.aligned.m16n8k16.row.col.f32.f16.f16.f32 "
                 "{%0,%1,%2,%3}, {%4,%5,%6,%7}, {%8,%9}, {%0,%1,%2,%3};"
                 : "+f"(d[0]), "+f"(d[1]), "+f"(d[2]), "+f"(d[3])
                 : "r"(a[0]), "r"(a[1]), "r"(a[2]), "r"(a[3]), "r"(b[0]), "r"(b[1]));
}
__device__ __forceinline__ void cp16(uint32_t dst, const void* src, bool valid) {
    int sz = valid ? 16 : 0;
    asm volatile("cp.async.cg.shared.global [%0], [%1], 16, %2;"
                 :: "r"(dst), "l"(src), "r"(sz));
}
__device__ __forceinline__ void cp_commit() {
    asm volatile("cp.async.commit_group;" ::: "memory");
}
__device__ __forceinline__ void cp_wait1() {
    asm volatile("cp.async.wait_group 1;" ::: "memory");
}
__device__ __forceinline__ void cp_wait0() {
    asm volatile("cp.async.wait_group 0;" ::: "memory");
}
__device__ __forceinline__ uint32_t pack2h(float a, float b) {
    __half2 p = __halves2half2(__float2half(a), __float2half(b));
    return *(uint32_t*)&p;
}

// ---------------- router / routing ----------------
__global__ void zero_counts_kernel() { if (threadIdx.x < EE) d_counts[threadIdx.x] = 0; }

__global__ void router_kernel(const float* __restrict__ x,
                              const float* __restrict__ rw,
                              const float* __restrict__ bias) {
    int warp = (blockIdx.x * blockDim.x + threadIdx.x) >> 5;
    int lane = threadIdx.x & 31;
    if (warp >= TT) return;
    const float* xr = x + (size_t)warp * HH;
    float acc[EE];
#pragma unroll
    for (int e = 0; e < EE; e++) acc[e] = 0.f;
    for (int h = lane; h < HH; h += 32) {
        float xv = __ldg(xr + h);
#pragma unroll
        for (int e = 0; e < EE; e++) acc[e] += xv * __ldg(rw + (size_t)e * HH + h);
    }
#pragma unroll
    for (int e = 0; e < EE; e++) {
        float v = acc[e];
#pragma unroll
        for (int o = 16; o > 0; o >>= 1) v += __shfl_xor_sync(0xffffffffu, v, o);
        acc[e] = v + bias[e];
    }
    if (lane == 0) {
        int idx[TOPK]; float lg[TOPK];
        unsigned used = 0;
        for (int k = 0; k < TOPK; k++) {
            float best = -INFINITY; int bi = 0;
            for (int e = 0; e < EE; e++) {
                if ((used >> e) & 1u) continue;
                if (acc[e] > best) { best = acc[e]; bi = e; }
            }
            used |= 1u << bi; idx[k] = bi; lg[k] = best;
        }
        float mx = lg[0], w[TOPK], s = 0.f;
        for (int k = 0; k < TOPK; k++) { w[k] = expf(lg[k] - mx); s += w[k]; }
        float inv = 1.f / s;
        for (int k = 0; k < TOPK; k++) {
            d_topi[warp * TOPK + k] = idx[k];
            d_topw[warp * TOPK + k] = w[k] * inv;
            atomicAdd(&d_counts[idx[k]], 1);
        }
    }
}

__global__ void scan_kernel() {
    int off = 0;
    for (int e = 0; e < EE; e++) { d_offsets[e] = off; d_cursors[e] = off; off += d_counts[e]; }
}

__global__ void assign_kernel() {
    int t = blockIdx.x * blockDim.x + threadIdx.x;
    if (t >= TT) return;
    for (int k = 0; k < TOPK; k++) {
        int e = d_topi[t * TOPK + k];
        int pos = atomicAdd(&d_cursors[e], 1);
        d_rows[pos] = t;
        d_posof[t * TOPK + k] = pos;
    }
}

// ---------------- convert x to fp16 ----------------
__global__ void conv_x_kernel(const float* __restrict__ x) {
    size_t i = ((size_t)blockIdx.x * blockDim.x + threadIdx.x) * 4;
    if (i >= (size_t)TT * HH) return;
    float4 v = *(const float4*)(x + i);
    uint2 hu;
    hu.x = pack2h(v.x, v.y);
    hu.y = pack2h(v.z, v.w);
    *(uint2*)&d_xh[i] = hu;
}

// ---------------- pipelined GEMM (mma.sync fp16, single precision each op) ----------------
#define BK 32

// per-stage smem layout (bytes)
#define S_AH   0          // 128 x 80B = 10240
#define S_BST  10240      // staged fp32 B: 2 mats x 32 rows x 272B = 17408
#define S_B0H  27648      // fp16 B mat0: 32 x 144B = 4608
#define S_B1H  32256      // fp16 B mat1: 32 x 144B = 4608
#define STAGE_BYTES 36864
#define SM_STAGE0 1024    // [0:512) rowidx
#define SMEM_TOTAL (SM_STAGE0 + 2*STAGE_BYTES)

template<int MODE>
__global__ __launch_bounds__(256, 2)
void moe_gemm(const float* __restrict__ Aext,
              const float* __restrict__ W0,
              const float* __restrict__ W1)
{
    constexpr int Kd  = (MODE == 0) ? HH : II;
    constexpr int ldB = (MODE == 0) ? II : HH;
    constexpr int NK  = Kd / BK;

    extern __shared__ __align__(16) char sm[];

    int e = blockIdx.z;
    int cnt = d_counts[e];
    int mblk = blockIdx.y;
    if (mblk * 128 >= cnt) return;
    int off = d_offsets[e];
    int nb = blockIdx.x * ((MODE == 0) ? 64 : 128);

    const float* B0; const float* B1;
    if (MODE == 0) {
        B0 = W0 + (size_t)e * HH * II + nb;
        B1 = W1 + (size_t)e * HH * II + nb;
    } else {
        B0 = W0 + (size_t)e * II * HH + nb;
        B1 = B0 + 64;
    }
    const __half* srcH = (MODE == 0) ? d_xh : d_ACTh;

    int tid = threadIdx.x, wid = tid >> 5, lane = tid & 31;

    // cache gathered row indices (-1 = invalid)
    int* rowIdx = (int*)sm;
    if (tid < 128) {
        int lr = mblk * 128 + tid;
        int r = -1;
        if (lr < cnt) r = (MODE == 0) ? d_rows[off + lr] : (off + lr);
        rowIdx[tid] = r;
    }
    __syncthreads();

    uint32_t smb = smem_u32(sm);

    auto load_stage = [&](int s, int kc) {
        uint32_t sb = smb + SM_STAGE0 + s * STAGE_BYTES;
        // A: 128 rows x 32 k fp16; 4 x 16B segs per row = 512 cp16
#pragma unroll
        for (int i = 0; i < 2; i++) {
            int slot = tid + 256 * i;
            int row = slot >> 2, seg = slot & 3;
            int r = rowIdx[row];
            bool v = r >= 0;
            size_t go = (size_t)(v ? r : 0) * Kd + kc * BK + seg * 8;
            cp16(sb + S_AH + row * 80 + seg * 16, srcH + go, v);
        }
        // B fp32: 2 mats x 32 rows x 64 floats; 16 x 16B segs per row
#pragma unroll
        for (int i = 0; i < 4; i++) {
            int slot = tid + 256 * i;
            int mat = slot >> 9, rem = slot & 511;
            int row = rem >> 4, seg = rem & 15;
            const float* src = (mat ? B1 : B0) + (size_t)(kc * BK + row) * ldB + seg * 4;
            cp16(sb + S_BST + mat * 8704 + row * 272 + seg * 16, src, true);
        }
        cp_commit();
    };

    auto convert_stage = [&](int s) {
        char* sbp = sm + SM_STAGE0 + s * STAGE_BYTES;
        // 2 mats x 32 rows x 64 floats = 4096 elems, 16 per thread
        int mat = tid >> 7, row = (tid >> 2) & 31, q = tid & 3;
        const char* srcb = sbp + S_BST + mat * 8704 + row * 272 + q * 64;
        uint32_t o[8];
#pragma unroll
        for (int i = 0; i < 4; i++) {
            float4 v = *(const float4*)(srcb + i * 16);
            o[i * 2]     = pack2h(v.x, v.y);
            o[i * 2 + 1] = pack2h(v.z, v.w);
        }
        char* dh = sbp + (mat ? S_B1H : S_B0H) + row * 144 + q * 32;
        *(uint4*)dh        = make_uint4(o[0], o[1], o[2], o[3]);
        *(uint4*)(dh + 16) = make_uint4(o[4], o[5], o[6], o[7]);
    };

    // ---- warp MMA layout (validated rounds 1/6/9) ----
    int wm = wid & 3, wn = wid >> 2;
    int sub = lane >> 3, lr = lane & 7;
    int a_row0 = wm * 32 + ((sub & 1) << 3) + lr;
    int a_kc   = (sub >> 1) << 3;
    int b_krow = (((lane >> 3) & 1) << 3) + lr;
    int b_nc0  = wn * 32;

    float acc0[2][4][4], acc1[2][4][4];
#pragma unroll
    for (int i = 0; i < 2; i++)
#pragma unroll
        for (int j = 0; j < 4; j++)
#pragma unroll
            for (int c = 0; c < 4; c++) { acc0[i][j][c] = 0.f; acc1[i][j][c] = 0.f; }

    auto mma_stage = [&](int s) {
        uint32_t sb = smb + SM_STAGE0 + s * STAGE_BYTES;
#pragma unroll
        for (int ck = 0; ck < 2; ck++) {
            uint32_t ah[2][4];
#pragma unroll
            for (int am = 0; am < 2; am++) {
                int row = a_row0 + am * 16;
                int col = ck * 16 + a_kc;
                ldsm_x4(ah[am], sb + S_AH + row * 80 + col * 2);
            }
            {
                uint32_t bh[4][2];
#pragma unroll
                for (int an = 0; an < 4; an++) {
                    int krow = ck * 16 + b_krow;
                    int ncol = b_nc0 + an * 8;
                    ldsm_x2t(bh[an], sb + S_B0H + krow * 144 + ncol * 2);
                }
#pragma unroll
                for (int am = 0; am < 2; am++)
#pragma unroll
                    for (int an = 0; an < 4; an++)
                        mma_f16(acc0[am][an], ah[am], bh[an]);
            }
            {
                uint32_t bh[4][2];
#pragma unroll
                for (int an = 0; an < 4; an++) {
                    int krow = ck * 16 + b_krow;
                    int ncol = b_nc0 + an * 8;
                    ldsm_x2t(bh[an], sb + S_B1H + krow * 144 + ncol * 2);
                }
#pragma unroll
                for (int am = 0; am < 2; am++)
#pragma unroll
                    for (int an = 0; an < 4; an++)
                        mma_f16(acc1[am][an], ah[am], bh[an]);
            }
        }
    };

    // ---- software pipeline (wait -> BARRIER -> read) ----
    load_stage(0, 0);
    load_stage(1, 1);
    cp_wait1();
    __syncthreads();
    convert_stage(0);
    __syncthreads();

    for (int kc = 0; kc < NK; kc++) {
        int cur = kc & 1;
        mma_stage(cur);
        __syncthreads();
        if (kc + 1 < NK) {
            if (kc + 2 < NK) { load_stage(cur, kc + 2); cp_wait1(); }
            else cp_wait0();
            __syncthreads();
            convert_stage((kc + 1) & 1);
            __syncthreads();
        }
    }

    // ---- epilogue ----
    int lrow = lane >> 2;
    int lcol = (lane & 3) << 1;
#pragma unroll
    for (int am = 0; am < 2; am++) {
#pragma unroll
        for (int hf = 0; hf < 2; hf++) {
            int row = wm * 32 + am * 16 + hf * 8 + lrow;
            int gm = mblk * 128 + row;
            if (gm >= cnt) continue;
            if (MODE == 0) {
                size_t base = (size_t)(off + gm) * II + nb + wn * 32 + lcol;
#pragma unroll
                for (int an = 0; an < 4; an++) {
                    float g0 = acc0[am][an][hf * 2],     u0 = acc1[am][an][hf * 2];
                    float g1 = acc0[am][an][hf * 2 + 1], u1 = acc1[am][an][hf * 2 + 1];
                    float a0 = g0 / (1.f + expf(-g0)) * u0;
                    float a1 = g1 / (1.f + expf(-g1)) * u1;
                    *(uint32_t*)&d_ACTh[base + an * 8] = pack2h(a0, a1);
                }
            } else {
                size_t base = (size_t)(off + gm) * HH + nb + wn * 32 + lcol;
#pragma unroll
                for (int an = 0; an < 4; an++) {
                    *(float2*)&d_Y[base + an * 8] =
                        make_float2(acc0[am][an][hf * 2], acc0[am][an][hf * 2 + 1]);
                    *(float2*)&d_Y[base + 64 + an * 8] =
                        make_float2(acc1[am][an][hf * 2], acc1[am][an][hf * 2 + 1]);
                }
            }
        }
    }
}

// ---------------- combine ----------------
__global__ void combine_kernel(float* __restrict__ out) {
    int t = blockIdx.x;
    float w[TOPK]; int p[TOPK];
#pragma unroll
    for (int k = 0; k < TOPK; k++) {
        w[k] = d_topw[t * TOPK + k];
        p[k] = d_posof[t * TOPK + k];
    }
    for (int h = threadIdx.x * 4; h < HH; h += blockDim.x * 4) {
        float4 s = make_float4(0, 0, 0, 0);
#pragma unroll
        for (int k = 0; k < TOPK; k++) {
            float4 y = *(const float4*)&d_Y[(size_t)p[k] * HH + h];
            s.x += w[k] * y.x; s.y += w[k] * y.y;
            s.z += w[k] * y.z; s.w += w[k] * y.w;
        }
        *(float4*)&out[(size_t)t * HH + h] = s;
    }
}

// ---------------- launch ----------------
extern "C" void kernel_launch(void* const* d_in, const int* in_sizes, int n_in,
                              void* d_out, int out_size) {
    const float* x    = (const float*)d_in[0];
    const float* rw   = (const float*)d_in[1];
    const float* bias = (const float*)d_in[2];
    const float* gate = (const float*)d_in[3];
    const float* up   = (const float*)d_in[4];
    const float* down = (const float*)d_in[5];
    float* out = (float*)d_out;

    cudaFuncSetAttribute(moe_gemm<0>, cudaFuncAttributeMaxDynamicSharedMemorySize, SMEM_TOTAL);
    cudaFuncSetAttribute(moe_gemm<1>, cudaFuncAttributeMaxDynamicSharedMemorySize, SMEM_TOTAL);

    zero_counts_kernel<<<1, 32>>>();
    router_kernel<<<TT / 8, 256>>>(x, rw, bias);
    scan_kernel<<<1, 1>>>();
    assign_kernel<<<TT / 256, 256>>>();
    conv_x_kernel<<<(TT * HH / 4 + 255) / 256, 256>>>(x);

    // fused gate+up (+SiLU, fp16 ACT): x = II/64 n-tiles, y = m-tiles, z = experts
    moe_gemm<0><<<dim3(II / 64, 16, EE), 256, SMEM_TOTAL>>>(x, gate, up);
    // down: x = HH/128 n-tiles
    moe_gemm<1><<<dim3(HH / 128, 16, EE), 256, SMEM_TOTAL>>>(nullptr, down, nullptr);

    combine_kernel<<<TT, 256>>>(out);
}

// round 12
// speedup vs baseline: 2.1263x; 1.1605x over previous
#include <cuda_runtime.h>
#include <cuda_fp16.h>
#include <math.h>
#include <stdint.h>

// Problem constants
#define TT 2048
#define HH 2048
#define II 1792
#define EE 16
#define TOPK 4
#define RR (TT*TOPK)

// ---------------- scratch ----------------
__device__ __half d_xh[(size_t)TT * HH];
__device__ __half d_ACTh[(size_t)RR * II];
__device__ float d_Y[(size_t)RR * HH];
__device__ __half d_g16[(size_t)EE * HH * II];
__device__ __half d_u16[(size_t)EE * HH * II];
__device__ __half d_d16[(size_t)EE * II * HH];
__device__ int   d_counts[EE];
__device__ int   d_offsets[EE];
__device__ int   d_cursors[EE];
__device__ int   d_rows[RR];
__device__ int   d_posof[TT * TOPK];
__device__ float d_topw[TT * TOPK];
__device__ int   d_topi[TT * TOPK];

// ---------------- helpers ----------------
__device__ __forceinline__ uint32_t smem_u32(const void* p) {
    return (uint32_t)__cvta_generic_to_shared(p);
}
__device__ __forceinline__ void ldsm_x4(uint32_t* r, uint32_t addr) {
    asm volatile("ldmatrix.sync.aligned.m8n8.x4.shared.b16 {%0,%1,%2,%3}, [%4];"
                 : "=r"(r[0]), "=r"(r[1]), "=r"(r[2]), "=r"(r[3]) : "r"(addr));
}
__device__ __forceinline__ void ldsm_x2t(uint32_t* r, uint32_t addr) {
    asm volatile("ldmatrix.sync.aligned.m8n8.x2.trans.shared.b16 {%0,%1}, [%2];"
                 : "=r"(r[0]), "=r"(r[1]) : "r"(addr));
}
__device__ __forceinline__ void mma_f16(float* d, const uint32_t* a, const uint32_t* b) {
    asm volatile("mma.sync.aligned.m16n8k16.row.col.f32.f16.f16.f32 "
                 "{%0,%1,%2,%3}, {%4,%5,%6,%7}, {%8,%9}, {%0,%1,%2,%3};"
                 : "+f"(d[0]), "+f"(d[1]), "+f"(d[2]), "+f"(d[3])
                 : "r"(a[0]), "r"(a[1]), "r"(a[2]), "r"(a[3]), "r"(b[0]), "r"(b[1]));
}
__device__ __forceinline__ void cp16(uint32_t dst, const void* src, bool valid) {
    int sz = valid ? 16 : 0;
    asm volatile("cp.async.cg.shared.global [%0], [%1], 16, %2;"
                 :: "r"(dst), "l"(src), "r"(sz));
}
__device__ __forceinline__ void cp_commit() {
    asm volatile("cp.async.commit_group;" ::: "memory");
}
__device__ __forceinline__ void cp_wait1() {
    asm volatile("cp.async.wait_group 1;" ::: "memory");
}
__device__ __forceinline__ void cp_wait0() {
    asm volatile("cp.async.wait_group 0;" ::: "memory");
}
__device__ __forceinline__ uint32_t pack2h(float a, float b) {
    __half2 p = __halves2half2(__float2half(a), __float2half(b));
    return *(uint32_t*)&p;
}

// ---------------- router / routing ----------------
__global__ void zero_counts_kernel() { if (threadIdx.x < EE) d_counts[threadIdx.x] = 0; }

__global__ void router_kernel(const float* __restrict__ x,
                              const float* __restrict__ rw,
                              const float* __restrict__ bias) {
    int warp = (blockIdx.x * blockDim.x + threadIdx.x) >> 5;
    int lane = threadIdx.x & 31;
    if (warp >= TT) return;
    const float* xr = x + (size_t)warp * HH;
    float acc[EE];
#pragma unroll
    for (int e = 0; e < EE; e++) acc[e] = 0.f;
    for (int h = lane; h < HH; h += 32) {
        float xv = __ldg(xr + h);
#pragma unroll
        for (int e = 0; e < EE; e++) acc[e] += xv * __ldg(rw + (size_t)e * HH + h);
    }
#pragma unroll
    for (int e = 0; e < EE; e++) {
        float v = acc[e];
#pragma unroll
        for (int o = 16; o > 0; o >>= 1) v += __shfl_xor_sync(0xffffffffu, v, o);
        acc[e] = v + bias[e];
    }
    if (lane == 0) {
        int idx[TOPK]; float lg[TOPK];
        unsigned used = 0;
        for (int k = 0; k < TOPK; k++) {
            float best = -INFINITY; int bi = 0;
            for (int e = 0; e < EE; e++) {
                if ((used >> e) & 1u) continue;
                if (acc[e] > best) { best = acc[e]; bi = e; }
            }
            used |= 1u << bi; idx[k] = bi; lg[k] = best;
        }
        float mx = lg[0], w[TOPK], s = 0.f;
        for (int k = 0; k < TOPK; k++) { w[k] = expf(lg[k] - mx); s += w[k]; }
        float inv = 1.f / s;
        for (int k = 0; k < TOPK; k++) {
            d_topi[warp * TOPK + k] = idx[k];
            d_topw[warp * TOPK + k] = w[k] * inv;
            atomicAdd(&d_counts[idx[k]], 1);
        }
    }
}

__global__ void scan_kernel() {
    int off = 0;
    for (int e = 0; e < EE; e++) { d_offsets[e] = off; d_cursors[e] = off; off += d_counts[e]; }
}

__global__ void assign_kernel() {
    int t = blockIdx.x * blockDim.x + threadIdx.x;
    if (t >= TT) return;
    for (int k = 0; k < TOPK; k++) {
        int e = d_topi[t * TOPK + k];
        int pos = atomicAdd(&d_cursors[e], 1);
        d_rows[pos] = t;
        d_posof[t * TOPK + k] = pos;
    }
}

// ---------------- convert x to fp16 ----------------
__global__ void conv_x_kernel(const float* __restrict__ x) {
    size_t i = ((size_t)blockIdx.x * blockDim.x + threadIdx.x) * 4;
    if (i >= (size_t)TT * HH) return;
    float4 v = *(const float4*)(x + i);
    uint2 hu;
    hu.x = pack2h(v.x, v.y);
    hu.y = pack2h(v.z, v.w);
    *(uint2*)&d_xh[i] = hu;
}

// ---------------- convert weights to fp16 (once per launch) ----------------
// All three weight tensors have the same element count: EE*HH*II == EE*II*HH.
template<int W>
__global__ void conv_w_kernel(const float* __restrict__ src) {
    __half* dst = (W == 0) ? d_g16 : (W == 1) ? d_u16 : d_d16;
    size_t i = (size_t)blockIdx.x * blockDim.x + threadIdx.x;   // one float4 per thread
    float4 v = ((const float4*)src)[i];
    uint2 h;
    h.x = pack2h(v.x, v.y);
    h.y = pack2h(v.z, v.w);
    ((uint2*)dst)[i] = h;
}

// ---------------- pipelined GEMM (fp16 mma.sync, 3-stage cp.async, BK=64) ----------------
#define BK 64

// per-stage smem layout (bytes); rows padded 128B+16B = 144B (conflict-free ldmatrix)
#define S_A    0          // 128 rows x 144B = 18432
#define S_B0   18432      // 64 k-rows x 144B = 9216
#define S_B1   27648      // 9216
#define STAGE_BYTES 36864
#define NSTAGE 3
#define SM_STAGE0 1024    // [0:512) rowidx
#define SMEM_TOTAL (SM_STAGE0 + NSTAGE*STAGE_BYTES)   // 111616 -> 2 CTAs/SM

// MODE 0: A = d_xh (gathered rows), B0 = d_g16[e](:,nb:nb+64), B1 = d_u16[e](:,nb:nb+64)
//         epilogue: d_ACTh = fp16(silu(g)*u)
// MODE 1: A = d_ACTh (direct), B0 = d_d16[e](:,nb:nb+64), B1 = +64
//         epilogue: d_Y fp32
template<int MODE>
__global__ __launch_bounds__(256, 2)
void moe_gemm()
{
    constexpr int Kd  = (MODE == 0) ? HH : II;
    constexpr int ldB = (MODE == 0) ? II : HH;
    constexpr int NK  = Kd / BK;   // 32 or 28

    extern __shared__ __align__(16) char sm[];

    int e = blockIdx.z;
    int cnt = d_counts[e];
    int mblk = blockIdx.y;
    if (mblk * 128 >= cnt) return;
    int off = d_offsets[e];
    int nb = blockIdx.x * ((MODE == 0) ? 64 : 128);

    const __half* B0; const __half* B1;
    if (MODE == 0) {
        B0 = d_g16 + (size_t)e * HH * II + nb;
        B1 = d_u16 + (size_t)e * HH * II + nb;
    } else {
        B0 = d_d16 + (size_t)e * II * HH + nb;
        B1 = B0 + 64;
    }
    const __half* srcH = (MODE == 0) ? d_xh : d_ACTh;

    int tid = threadIdx.x, wid = tid >> 5, lane = tid & 31;

    // cache gathered row indices (-1 = invalid)
    int* rowIdx = (int*)sm;
    if (tid < 128) {
        int lr = mblk * 128 + tid;
        int r = -1;
        if (lr < cnt) r = (MODE == 0) ? d_rows[off + lr] : (off + lr);
        rowIdx[tid] = r;
    }
    __syncthreads();

    uint32_t smb = smem_u32(sm);

    auto load_stage = [&](int s, int kc) {
        uint32_t sb = smb + SM_STAGE0 + s * STAGE_BYTES;
        // A: 128 rows x 64 fp16 (128B/row, 8 x 16B segs) = 1024 cp16, 4/thread
#pragma unroll
        for (int i = 0; i < 4; i++) {
            int slot = tid + 256 * i;
            int row = slot >> 3, seg = slot & 7;
            int r = rowIdx[row];
            bool v = r >= 0;
            size_t go = (size_t)(v ? r : 0) * Kd + kc * BK + seg * 8;
            cp16(sb + S_A + row * 144 + seg * 16, srcH + go, v);
        }
        // B: 2 mats x 64 k-rows x 64 n fp16 (8 segs/row) = 1024 cp16, 4/thread
#pragma unroll
        for (int i = 0; i < 4; i++) {
            int slot = tid + 256 * i;
            int mat = slot >> 9, rem = slot & 511;
            int row = rem >> 3, seg = rem & 7;
            const __half* src = (mat ? B1 : B0) + (size_t)(kc * BK + row) * ldB + seg * 8;
            cp16(sb + (mat ? S_B1 : S_B0) + row * 144 + seg * 16, src, true);
        }
        cp_commit();
    };

    // ---- warp MMA layout (validated rounds 1/6/9/10) ----
    int wm = wid & 3, wn = wid >> 2;
    int sub = lane >> 3, lr = lane & 7;
    int a_row0 = wm * 32 + ((sub & 1) << 3) + lr;
    int a_kc   = (sub >> 1) << 3;
    int b_krow = (((lane >> 3) & 1) << 3) + lr;
    int b_nc0  = wn * 32;

    float acc0[2][4][4], acc1[2][4][4];
#pragma unroll
    for (int i = 0; i < 2; i++)
#pragma unroll
        for (int j = 0; j < 4; j++)
#pragma unroll
            for (int c = 0; c < 4; c++) { acc0[i][j][c] = 0.f; acc1[i][j][c] = 0.f; }

    auto mma_stage = [&](int s) {
        uint32_t sb = smb + SM_STAGE0 + s * STAGE_BYTES;
#pragma unroll
        for (int ck = 0; ck < 4; ck++) {
            uint32_t ah[2][4];
#pragma unroll
            for (int am = 0; am < 2; am++) {
                int row = a_row0 + am * 16;
                int col = ck * 16 + a_kc;
                ldsm_x4(ah[am], sb + S_A + row * 144 + col * 2);
            }
            {
                uint32_t bh[4][2];
#pragma unroll
                for (int an = 0; an < 4; an++) {
                    int krow = ck * 16 + b_krow;
                    int ncol = b_nc0 + an * 8;
                    ldsm_x2t(bh[an], sb + S_B0 + krow * 144 + ncol * 2);
                }
#pragma unroll
                for (int am = 0; am < 2; am++)
#pragma unroll
                    for (int an = 0; an < 4; an++)
                        mma_f16(acc0[am][an], ah[am], bh[an]);
            }
            {
                uint32_t bh[4][2];
#pragma unroll
                for (int an = 0; an < 4; an++) {
                    int krow = ck * 16 + b_krow;
                    int ncol = b_nc0 + an * 8;
                    ldsm_x2t(bh[an], sb + S_B1 + krow * 144 + ncol * 2);
                }
#pragma unroll
                for (int am = 0; am < 2; am++)
#pragma unroll
                    for (int an = 0; an < 4; an++)
                        mma_f16(acc1[am][an], ah[am], bh[an]);
            }
        }
    };

    // ---- 3-stage pipeline, ONE barrier per iteration ----
    // iter kc: wait(stage kc complete) -> sync (also frees buffer of stage kc-1)
    //          -> load stage kc+2 into that freed buffer -> mma(kc)
    load_stage(0, 0);
    load_stage(1, 1);

    for (int kc = 0; kc < NK; kc++) {
        if (kc + 1 == NK) cp_wait0(); else cp_wait1();
        __syncthreads();
        if (kc + 2 < NK) load_stage((kc + 2) % NSTAGE, kc + 2);
        mma_stage(kc % NSTAGE);
    }

    // ---- epilogue ----
    int lrow = lane >> 2;
    int lcol = (lane & 3) << 1;
#pragma unroll
    for (int am = 0; am < 2; am++) {
#pragma unroll
        for (int hf = 0; hf < 2; hf++) {
            int row = wm * 32 + am * 16 + hf * 8 + lrow;
            int gm = mblk * 128 + row;
            if (gm >= cnt) continue;
            if (MODE == 0) {
                size_t base = (size_t)(off + gm) * II + nb + wn * 32 + lcol;
#pragma unroll
                for (int an = 0; an < 4; an++) {
                    float g0 = acc0[am][an][hf * 2],     u0 = acc1[am][an][hf * 2];
                    float g1 = acc0[am][an][hf * 2 + 1], u1 = acc1[am][an][hf * 2 + 1];
                    float a0 = g0 / (1.f + expf(-g0)) * u0;
                    float a1 = g1 / (1.f + expf(-g1)) * u1;
                    *(uint32_t*)&d_ACTh[base + an * 8] = pack2h(a0, a1);
                }
            } else {
                size_t base = (size_t)(off + gm) * HH + nb + wn * 32 + lcol;
#pragma unroll
                for (int an = 0; an < 4; an++) {
                    *(float2*)&d_Y[base + an * 8] =
                        make_float2(acc0[am][an][hf * 2], acc0[am][an][hf * 2 + 1]);
                    *(float2*)&d_Y[base + 64 + an * 8] =
                        make_float2(acc1[am][an][hf * 2], acc1[am][an][hf * 2 + 1]);
                }
            }
        }
    }
}

// ---------------- combine ----------------
__global__ void combine_kernel(float* __restrict__ out) {
    int t = blockIdx.x;
    float w[TOPK]; int p[TOPK];
#pragma unroll
    for (int k = 0; k < TOPK; k++) {
        w[k] = d_topw[t * TOPK + k];
        p[k] = d_posof[t * TOPK + k];
    }
    for (int h = threadIdx.x * 4; h < HH; h += blockDim.x * 4) {
        float4 s = make_float4(0, 0, 0, 0);
#pragma unroll
        for (int k = 0; k < TOPK; k++) {
            float4 y = *(const float4*)&d_Y[(size_t)p[k] * HH + h];
            s.x += w[k] * y.x; s.y += w[k] * y.y;
            s.z += w[k] * y.z; s.w += w[k] * y.w;
        }
        *(float4*)&out[(size_t)t * HH + h] = s;
    }
}

// ---------------- launch ----------------
extern "C" void kernel_launch(void* const* d_in, const int* in_sizes, int n_in,
                              void* d_out, int out_size) {
    const float* x    = (const float*)d_in[0];
    const float* rw   = (const float*)d_in[1];
    const float* bias = (const float*)d_in[2];
    const float* gate = (const float*)d_in[3];
    const float* up   = (const float*)d_in[4];
    const float* down = (const float*)d_in[5];
    float* out = (float*)d_out;

    cudaFuncSetAttribute(moe_gemm<0>, cudaFuncAttributeMaxDynamicSharedMemorySize, SMEM_TOTAL);
    cudaFuncSetAttribute(moe_gemm<1>, cudaFuncAttributeMaxDynamicSharedMemorySize, SMEM_TOTAL);

    zero_counts_kernel<<<1, 32>>>();
    router_kernel<<<TT / 8, 256>>>(x, rw, bias);
    scan_kernel<<<1, 1>>>();
    assign_kernel<<<TT / 256, 256>>>();
    conv_x_kernel<<<(TT * HH / 4 + 255) / 256, 256>>>(x);

    // weights -> fp16 (EE*HH*II/4 float4s = 14,680,064 -> 57,344 blocks exactly)
    const int WBLK = (int)((size_t)EE * HH * II / 4 / 256);
    conv_w_kernel<0><<<WBLK, 256>>>(gate);
    conv_w_kernel<1><<<WBLK, 256>>>(up);
    conv_w_kernel<2><<<WBLK, 256>>>(down);

    // fused gate+up (+SiLU, fp16 ACT): x = II/64 n-tiles, y = m-tiles, z = experts
    moe_gemm<0><<<dim3(II / 64, 16, EE), 256, SMEM_TOTAL>>>();
    // down: x = HH/128 n-tiles
    moe_gemm<1><<<dim3(HH / 128, 16, EE), 256, SMEM_TOTAL>>>();

    combine_kernel<<<TT, 256>>>(out);
}

// round 13
// speedup vs baseline: 2.3276x; 1.0946x over previous
#include <cuda_runtime.h>
#include <cuda_fp16.h>
#include <math.h>
#include <stdint.h>

// Problem constants
#define TT 2048
#define HH 2048
#define II 1792
#define EE 16
#define TOPK 4
#define RR (TT*TOPK)

// ---------------- scratch ----------------
__device__ __half d_xh[(size_t)TT * HH];
__device__ __half d_ACTh[(size_t)RR * II];
__device__ float d_Y[(size_t)RR * HH];
__device__ __half d_g16[(size_t)EE * HH * II];
__device__ __half d_u16[(size_t)EE * HH * II];
__device__ __half d_d16[(size_t)EE * II * HH];
__device__ int   d_counts[EE];
__device__ int   d_offsets[EE];
__device__ int   d_cursors[EE];
__device__ int   d_rows[RR];
__device__ int   d_posof[TT * TOPK];
__device__ float d_topw[TT * TOPK];
__device__ int   d_topi[TT * TOPK];

// ---------------- helpers ----------------
__device__ __forceinline__ uint32_t smem_u32(const void* p) {
    return (uint32_t)__cvta_generic_to_shared(p);
}
__device__ __forceinline__ void ldsm_x4(uint32_t* r, uint32_t addr) {
    asm volatile("ldmatrix.sync.aligned.m8n8.x4.shared.b16 {%0,%1,%2,%3}, [%4];"
                 : "=r"(r[0]), "=r"(r[1]), "=r"(r[2]), "=r"(r[3]) : "r"(addr));
}
__device__ __forceinline__ void ldsm_x4t(uint32_t* r, uint32_t addr) {
    asm volatile("ldmatrix.sync.aligned.m8n8.x4.trans.shared.b16 {%0,%1,%2,%3}, [%4];"
                 : "=r"(r[0]), "=r"(r[1]), "=r"(r[2]), "=r"(r[3]) : "r"(addr));
}
__device__ __forceinline__ void mma_f16(float* d, const uint32_t* a, const uint32_t* b) {
    asm volatile("mma.sync.aligned.m16n8k16.row.col.f32.f16.f16.f32 "
                 "{%0,%1,%2,%3}, {%4,%5,%6,%7}, {%8,%9}, {%0,%1,%2,%3};"
                 : "+f"(d[0]), "+f"(d[1]), "+f"(d[2]), "+f"(d[3])
                 : "r"(a[0]), "r"(a[1]), "r"(a[2]), "r"(a[3]), "r"(b[0]), "r"(b[1]));
}
__device__ __forceinline__ void cp16(uint32_t dst, const void* src, bool valid) {
    int sz = valid ? 16 : 0;
    asm volatile("cp.async.cg.shared.global [%0], [%1], 16, %2;"
                 :: "r"(dst), "l"(src), "r"(sz));
}
__device__ __forceinline__ void cp_commit() {
    asm volatile("cp.async.commit_group;" ::: "memory");
}
__device__ __forceinline__ void cp_wait1() {
    asm volatile("cp.async.wait_group 1;" ::: "memory");
}
__device__ __forceinline__ void cp_wait0() {
    asm volatile("cp.async.wait_group 0;" ::: "memory");
}
__device__ __forceinline__ uint32_t pack2h(float a, float b) {
    __half2 p = __halves2half2(__float2half(a), __float2half(b));
    return *(uint32_t*)&p;
}
__device__ __forceinline__ void conv_f4(const float4* src, uint2* dst, size_t i) {
    float4 v = src[i];
    uint2 h;
    h.x = pack2h(v.x, v.y);
    h.y = pack2h(v.z, v.w);
    dst[i] = h;
}

// ---------------- routing ----------------
__global__ void zero_counts_kernel() { if (threadIdx.x < EE) d_counts[threadIdx.x] = 0; }

// Fused prep: router (blocks [0,256)) + x->fp16 (blocks [256,1280))
//           + gate/up weights->fp16 (blocks [1280,5376))
#define PREP_ROUTER 256
#define PREP_CONVX  1024
#define PREP_CONVW  4096
#define PREP_GRID   (PREP_ROUTER + PREP_CONVX + PREP_CONVW)
__global__ __launch_bounds__(256)
void prep_kernel(const float* __restrict__ x,
                 const float* __restrict__ rw,
                 const float* __restrict__ bias,
                 const float* __restrict__ gate,
                 const float* __restrict__ up) {
    int b = blockIdx.x;
    if (b >= PREP_ROUTER + PREP_CONVX) {
        // --- gate/up weight conversion: 2 x 14,680,064 float4, 4096 blocks x 7168 ---
        int c = b - PREP_ROUTER - PREP_CONVX;
        const float4* src;
        uint2* dst;
        size_t base;
        if (c < PREP_CONVW / 2) {
            src = (const float4*)gate; dst = (uint2*)d_g16;
            base = (size_t)c * 7168;
        } else {
            src = (const float4*)up; dst = (uint2*)d_u16;
            base = (size_t)(c - PREP_CONVW / 2) * 7168;
        }
#pragma unroll
        for (int i = 0; i < 28; i++)
            conv_f4(src, dst, base + threadIdx.x + 256 * i);
        return;
    }
    if (b >= PREP_ROUTER) {
        // --- x conversion: 1,048,576 float4, 1024 blocks x 1024 ---
        size_t base = (size_t)(b - PREP_ROUTER) * 1024;
#pragma unroll
        for (int i = 0; i < 4; i++)
            conv_f4((const float4*)x, (uint2*)d_xh, base + threadIdx.x + 256 * i);
        return;
    }
    // --- router: warp per token ---
    int warp = (b * blockDim.x + threadIdx.x) >> 5;
    int lane = threadIdx.x & 31;
    const float* xr = x + (size_t)warp * HH;
    float acc[EE];
#pragma unroll
    for (int e = 0; e < EE; e++) acc[e] = 0.f;
    for (int h = lane; h < HH; h += 32) {
        float xv = __ldg(xr + h);
#pragma unroll
        for (int e = 0; e < EE; e++) acc[e] += xv * __ldg(rw + (size_t)e * HH + h);
    }
#pragma unroll
    for (int e = 0; e < EE; e++) {
        float v = acc[e];
#pragma unroll
        for (int o = 16; o > 0; o >>= 1) v += __shfl_xor_sync(0xffffffffu, v, o);
        acc[e] = v + bias[e];
    }
    if (lane == 0) {
        int idx[TOPK]; float lg[TOPK];
        unsigned used = 0;
        for (int k = 0; k < TOPK; k++) {
            float best = -INFINITY; int bi = 0;
            for (int e = 0; e < EE; e++) {
                if ((used >> e) & 1u) continue;
                if (acc[e] > best) { best = acc[e]; bi = e; }
            }
            used |= 1u << bi; idx[k] = bi; lg[k] = best;
        }
        float mx = lg[0], w[TOPK], s = 0.f;
        for (int k = 0; k < TOPK; k++) { w[k] = expf(lg[k] - mx); s += w[k]; }
        float inv = 1.f / s;
        for (int k = 0; k < TOPK; k++) {
            d_topi[warp * TOPK + k] = idx[k];
            d_topw[warp * TOPK + k] = w[k] * inv;
            atomicAdd(&d_counts[idx[k]], 1);
        }
    }
}

__global__ void scan_kernel() {
    int off = 0;
    for (int e = 0; e < EE; e++) { d_offsets[e] = off; d_cursors[e] = off; off += d_counts[e]; }
}

__global__ void assign_kernel() {
    int t = blockIdx.x * blockDim.x + threadIdx.x;
    if (t >= TT) return;
    for (int k = 0; k < TOPK; k++) {
        int e = d_topi[t * TOPK + k];
        int pos = atomicAdd(&d_cursors[e], 1);
        d_rows[pos] = t;
        d_posof[t * TOPK + k] = pos;
    }
}

// ---------------- pipelined GEMM (fp16 mma.sync, 3-stage cp.async, BK=64) ----------------
#define BK 64
#define S_A    0          // 128 rows x 144B = 18432
#define S_B0   18432      // 64 k-rows x 144B = 9216
#define S_B1   27648
#define STAGE_BYTES 36864
#define NSTAGE 3
#define SM_STAGE0 1024
#define SMEM_TOTAL (SM_STAGE0 + NSTAGE*STAGE_BYTES)   // 111616 -> 2 CTAs/SM

#define MT 8   // m-tiles per expert (counts are 512 +/- ~22; 8*128=1024 is a 15-sigma bound)

// MODE 0: A = d_xh (gathered), B0 = d_g16[e], B1 = d_u16[e]; epilogue: ACT = fp16(silu(g)*u).
//         Additionally each block converts a slice of the down weights (overlapped w/ compute).
// MODE 1: A = d_ACTh (direct), B0/B1 = d_d16[e] (two 64-col halves); epilogue: Y fp32.
template<int MODE>
__global__ __launch_bounds__(256, 2)
void moe_gemm(const float* __restrict__ downW)
{
    constexpr int Kd  = (MODE == 0) ? HH : II;
    constexpr int ldB = (MODE == 0) ? II : HH;
    constexpr int NK  = Kd / BK;

    extern __shared__ __align__(16) char sm[];

    int tid = threadIdx.x, wid = tid >> 5, lane = tid & 31;

    if (MODE == 0) {
        // convert this block's slice of down weights: 3584 blocks x 4096 float4
        int flat = (blockIdx.z * gridDim.y + blockIdx.y) * gridDim.x + blockIdx.x;
        size_t base = (size_t)flat * 4096;
#pragma unroll
        for (int i = 0; i < 16; i++)
            conv_f4((const float4*)downW, (uint2*)d_d16, base + tid + 256 * i);
    }

    int e = blockIdx.z;
    int cnt = d_counts[e];
    int mblk = blockIdx.y;
    if (mblk * 128 >= cnt) return;
    int off = d_offsets[e];
    int nb = blockIdx.x * ((MODE == 0) ? 64 : 128);

    const __half* B0; const __half* B1;
    if (MODE == 0) {
        B0 = d_g16 + (size_t)e * HH * II + nb;
        B1 = d_u16 + (size_t)e * HH * II + nb;
    } else {
        B0 = d_d16 + (size_t)e * II * HH + nb;
        B1 = B0 + 64;
    }
    const __half* srcH = (MODE == 0) ? d_xh : d_ACTh;

    // cache gathered row indices (-1 = invalid)
    int* rowIdx = (int*)sm;
    if (tid < 128) {
        int lr = mblk * 128 + tid;
        int r = -1;
        if (lr < cnt) r = (MODE == 0) ? d_rows[off + lr] : (off + lr);
        rowIdx[tid] = r;
    }
    __syncthreads();

    uint32_t smb = smem_u32(sm);

    auto load_stage = [&](int s, int kc) {
        uint32_t sb = smb + SM_STAGE0 + s * STAGE_BYTES;
#pragma unroll
        for (int i = 0; i < 4; i++) {
            int slot = tid + 256 * i;
            int row = slot >> 3, seg = slot & 7;
            int r = rowIdx[row];
            bool v = r >= 0;
            size_t go = (size_t)(v ? r : 0) * Kd + kc * BK + seg * 8;
            cp16(sb + S_A + row * 144 + seg * 16, srcH + go, v);
        }
#pragma unroll
        for (int i = 0; i < 4; i++) {
            int slot = tid + 256 * i;
            int mat = slot >> 9, rem = slot & 511;
            int row = rem >> 3, seg = rem & 7;
            const __half* src = (mat ? B1 : B0) + (size_t)(kc * BK + row) * ldB + seg * 8;
            cp16(sb + (mat ? S_B1 : S_B0) + row * 144 + seg * 16, src, true);
        }
        cp_commit();
    };

    // ---- warp MMA layout ----
    int wm = wid & 3, wn = wid >> 2;
    int sub = lane >> 3, lr = lane & 7;
    int a_row0 = wm * 32 + ((sub & 1) << 3) + lr;
    int a_kc   = (sub >> 1) << 3;
    int b_krow = (((lane >> 3) & 1) << 3) + lr;   // rows within 16-k chunk
    int b_nc0  = wn * 32;
    int b_cx   = (lane >> 4) << 3;                // x4t: second n-pair column offset

    float acc0[2][4][4], acc1[2][4][4];
#pragma unroll
    for (int i = 0; i < 2; i++)
#pragma unroll
        for (int j = 0; j < 4; j++)
#pragma unroll
            for (int c = 0; c < 4; c++) { acc0[i][j][c] = 0.f; acc1[i][j][c] = 0.f; }

    auto mma_stage = [&](int s) {
        uint32_t sb = smb + SM_STAGE0 + s * STAGE_BYTES;
#pragma unroll
        for (int ck = 0; ck < 4; ck++) {
            uint32_t ah[2][4];
#pragma unroll
            for (int am = 0; am < 2; am++) {
                int row = a_row0 + am * 16;
                int col = ck * 16 + a_kc;
                ldsm_x4(ah[am], sb + S_A + row * 144 + col * 2);
            }
            {
                uint32_t bh[4][2];
#pragma unroll
                for (int an = 0; an < 4; an += 2) {
                    int krow = ck * 16 + b_krow;
                    int ncol = b_nc0 + an * 8 + b_cx;
                    ldsm_x4t(&bh[an][0], sb + S_B0 + krow * 144 + ncol * 2);
                }
#pragma unroll
                for (int am = 0; am < 2; am++)
#pragma unroll
                    for (int an = 0; an < 4; an++)
                        mma_f16(acc0[am][an], ah[am], bh[an]);
            }
            {
                uint32_t bh[4][2];
#pragma unroll
                for (int an = 0; an < 4; an += 2) {
                    int krow = ck * 16 + b_krow;
                    int ncol = b_nc0 + an * 8 + b_cx;
                    ldsm_x4t(&bh[an][0], sb + S_B1 + krow * 144 + ncol * 2);
                }
#pragma unroll
                for (int am = 0; am < 2; am++)
#pragma unroll
                    for (int an = 0; an < 4; an++)
                        mma_f16(acc1[am][an], ah[am], bh[an]);
            }
        }
    };

    // ---- 3-stage pipeline, one barrier per iteration ----
    load_stage(0, 0);
    load_stage(1, 1);
    for (int kc = 0; kc < NK; kc++) {
        if (kc + 1 == NK) cp_wait0(); else cp_wait1();
        __syncthreads();
        if (kc + 2 < NK) load_stage((kc + 2) % NSTAGE, kc + 2);
        mma_stage(kc % NSTAGE);
    }

    // ---- epilogue ----
    int lrow = lane >> 2;
    int lcol = (lane & 3) << 1;
#pragma unroll
    for (int am = 0; am < 2; am++) {
#pragma unroll
        for (int hf = 0; hf < 2; hf++) {
            int row = wm * 32 + am * 16 + hf * 8 + lrow;
            int gm = mblk * 128 + row;
            if (gm >= cnt) continue;
            if (MODE == 0) {
                size_t base = (size_t)(off + gm) * II + nb + wn * 32 + lcol;
#pragma unroll
                for (int an = 0; an < 4; an++) {
                    float g0 = acc0[am][an][hf * 2],     u0 = acc1[am][an][hf * 2];
                    float g1 = acc0[am][an][hf * 2 + 1], u1 = acc1[am][an][hf * 2 + 1];
                    float a0 = g0 / (1.f + expf(-g0)) * u0;
                    float a1 = g1 / (1.f + expf(-g1)) * u1;
                    *(uint32_t*)&d_ACTh[base + an * 8] = pack2h(a0, a1);
                }
            } else {
                size_t base = (size_t)(off + gm) * HH + nb + wn * 32 + lcol;
#pragma unroll
                for (int an = 0; an < 4; an++) {
                    *(float2*)&d_Y[base + an * 8] =
                        make_float2(acc0[am][an][hf * 2], acc0[am][an][hf * 2 + 1]);
                    *(float2*)&d_Y[base + 64 + an * 8] =
                        make_float2(acc1[am][an][hf * 2], acc1[am][an][hf * 2 + 1]);
                }
            }
        }
    }
}

// ---------------- combine ----------------
__global__ void combine_kernel(float* __restrict__ out) {
    int t = blockIdx.x;
    float w[TOPK]; int p[TOPK];
#pragma unroll
    for (int k = 0; k < TOPK; k++) {
        w[k] = d_topw[t * TOPK + k];
        p[k] = d_posof[t * TOPK + k];
    }
    for (int h = threadIdx.x * 4; h < HH; h += blockDim.x * 4) {
        float4 s = make_float4(0, 0, 0, 0);
#pragma unroll
        for (int k = 0; k < TOPK; k++) {
            float4 y = *(const float4*)&d_Y[(size_t)p[k] * HH + h];
            s.x += w[k] * y.x; s.y += w[k] * y.y;
            s.z += w[k] * y.z; s.w += w[k] * y.w;
        }
        *(float4*)&out[(size_t)t * HH + h] = s;
    }
}

// ---------------- launch ----------------
extern "C" void kernel_launch(void* const* d_in, const int* in_sizes, int n_in,
                              void* d_out, int out_size) {
    const float* x    = (const float*)d_in[0];
    const float* rw   = (const float*)d_in[1];
    const float* bias = (const float*)d_in[2];
    const float* gate = (const float*)d_in[3];
    const float* up   = (const float*)d_in[4];
    const float* down = (const float*)d_in[5];
    float* out = (float*)d_out;

    cudaFuncSetAttribute(moe_gemm<0>, cudaFuncAttributeMaxDynamicSharedMemorySize, SMEM_TOTAL);
    cudaFuncSetAttribute(moe_gemm<1>, cudaFuncAttributeMaxDynamicSharedMemorySize, SMEM_TOTAL);

    zero_counts_kernel<<<1, 32>>>();
    prep_kernel<<<PREP_GRID, 256>>>(x, rw, bias, gate, up);
    scan_kernel<<<1, 1>>>();
    assign_kernel<<<TT / 256, 256>>>();

    // fused gate+up (+SiLU, fp16 ACT) + embedded down-weight conversion
    moe_gemm<0><<<dim3(II / 64, MT, EE), 256, SMEM_TOTAL>>>(down);
    // down GEMM
    moe_gemm<1><<<dim3(HH / 128, MT, EE), 256, SMEM_TOTAL>>>(nullptr);

    combine_kernel<<<TT, 256>>>(out);
}